// round 2
// baseline (speedup 1.0000x reference)
#include <cuda_runtime.h>
#include <cuda_bf16.h>
#include <stdint.h>

// out[i] = center[argmin_m |x[i] - center[m]|]
// Forward value of the soft-quantizer with straight-through estimator:
// (W_hard - W_soft) + W_soft == W_hard exactly, so only the hard path matters.

#define N_CENTERS 16

__device__ __forceinline__ float nearest_center(float v, const float* __restrict__ c) {
    // Two independent 8-deep chains, merged at the end. First minimum wins
    // (strict < within each chain; merge prefers chain A on ties, and chain A
    // holds the lower indices) — matches jnp.argmin tie-break.
    float dA = fabsf(v - c[0]);
    float vA = c[0];
    float dB = fabsf(v - c[8]);
    float vB = c[8];
#pragma unroll
    for (int m = 1; m < 8; ++m) {
        float da = fabsf(v - c[m]);
        bool ta = da < dA;
        dA = ta ? da : dA;
        vA = ta ? c[m] : vA;
        float db = fabsf(v - c[m + 8]);
        bool tb = db < dB;
        dB = tb ? db : dB;
        vB = tb ? c[m + 8] : vB;
    }
    // tie -> A (lower index) wins: only take B on strict <
    return (dB < dA) ? vB : vA;
}

__global__ void quantizer_kernel4(const float4* __restrict__ x4,
                                  const float* __restrict__ center,
                                  float4* __restrict__ out4,
                                  int n4) {
    __shared__ float c[N_CENTERS];
    if (threadIdx.x < N_CENTERS) c[threadIdx.x] = center[threadIdx.x];
    __syncthreads();

    int i = blockIdx.x * blockDim.x + threadIdx.x;
    if (i < n4) {
        float4 v = x4[i];
        float4 r;
        r.x = nearest_center(v.x, c);
        r.y = nearest_center(v.y, c);
        r.z = nearest_center(v.z, c);
        r.w = nearest_center(v.w, c);
        out4[i] = r;
    }
}

__global__ void quantizer_kernel1(const float* __restrict__ x,
                                  const float* __restrict__ center,
                                  float* __restrict__ out,
                                  int start, int n) {
    __shared__ float c[N_CENTERS];
    if (threadIdx.x < N_CENTERS) c[threadIdx.x] = center[threadIdx.x];
    __syncthreads();
    int i = start + blockIdx.x * blockDim.x + threadIdx.x;
    if (i < n) out[i] = nearest_center(x[i], c);
}

extern "C" void kernel_launch(void* const* d_in, const int* in_sizes, int n_in,
                              void* d_out, int out_size) {
    const float* x      = (const float*)d_in[0];
    const float* center = (const float*)d_in[1];
    float* out          = (float*)d_out;

    int n = in_sizes[0];
    const int TPB = 256;

    bool aligned = ((((uintptr_t)x) | ((uintptr_t)out)) & 0xF) == 0;
    if (aligned) {
        int n4 = n >> 2;
        if (n4 > 0) {
            int blocks = (n4 + TPB - 1) / TPB;
            quantizer_kernel4<<<blocks, TPB>>>((const float4*)x, center, (float4*)out, n4);
        }
        int tail_start = n4 << 2;
        if (n - tail_start > 0) {
            quantizer_kernel1<<<1, TPB>>>(x, center, out, tail_start, n);
        }
    } else {
        int blocks = (n + TPB - 1) / TPB;
        quantizer_kernel1<<<blocks, TPB>>>(x, center, out, 0, n);
    }
}

// round 3
// speedup vs baseline: 1.1802x; 1.1802x over previous
#include <cuda_runtime.h>
#include <cuda_bf16.h>
#include <stdint.h>
#include <math.h>

// out[i] = center[argmin_m |x[i] - center[m]|]  (exact jnp.argmin semantics,
// first-min wins). Forward value of the straight-through soft quantizer.
//
// Strategy: 15 Voronoi boundaries -> 4096-cell interval table. Each cell
// stores the (<=2) candidate centers, tie-ordered. Main kernel: 1 FMA + bit
// trick for the cell index, one LDS.64, one exact 2-way fp32 distance compare.

#define NC      16
#define NCELLS  4096

__device__ float2 g_cells[NCELLS];
__device__ float2 g_affine;  // {S, B}: u = fma(x, S, B) maps boundary span to [1,2)

// ---------------------------------------------------------------- prep ----
__global__ void prep_kernel(const float* __restrict__ center) {
    __shared__ float  s_val[NC];
    __shared__ int    s_orig[NC];
    __shared__ double s_thr[NC - 1];
    __shared__ float  s_SB[2];

    int t = threadIdx.x;

    // Stable rank sort of the 16 centers (equal values keep original order).
    if (t < NC) {
        float ct = center[t];
        int rank = 0;
        for (int j = 0; j < NC; ++j) {
            float cj = center[j];
            if (cj < ct || (cj == ct && j < t)) rank++;
        }
        s_val[rank]  = ct;
        s_orig[rank] = t;
    }
    __syncthreads();

    if (t == 0) {
        for (int r = 0; r < NC - 1; ++r)
            s_thr[r] = 0.5 * ((double)s_val[r] + (double)s_val[r + 1]);
        double lo = s_thr[0], hi = s_thr[NC - 2];
        float S, B;
        if (hi - lo > 1e-30) {
            S = (float)(1.0 / (hi - lo));
            B = (float)(1.0 - lo * (double)S);
        } else {           // degenerate: all cells -> slow path via sentinel
            S = 0.0f; B = 1.5f;
        }
        s_SB[0] = S; s_SB[1] = B;
        g_affine = make_float2(S, B);
    }
    __syncthreads();

    double S = (double)s_SB[0], B = (double)s_SB[1];
    const double slack = 4e-6;  // in u units; cell width = 2.44e-4; fp32 fma
                                // rounding in the main kernel is ~1e-7.

    for (int j = t; j < NCELLS; j += blockDim.x) {
        double xlo, xhi;
        if (S == 0.0) { xlo = -INFINITY; xhi = INFINITY; }
        else {
            xlo = (j == 0) ? -INFINITY
                 : ((1.0 + (double)j / NCELLS - slack) - B) / S;
            xhi = (j == NCELLS - 1) ? INFINITY
                 : ((1.0 + (double)(j + 1) / NCELLS + slack) - B) / S;
        }
        // klo = #thresholds fully below the cell; nb = #thresholds inside.
        int klo = 0, nb = 0;
        for (int r = 0; r < NC - 1; ++r) {
            double th = s_thr[r];
            if (th <= xlo) klo++;
            else if (th < xhi) nb++;
        }
        float2 pq;
        if (nb == 0) {
            pq.x = s_val[klo]; pq.y = s_val[klo];
        } else if (nb == 1) {
            // Tie-order: p (stored first) wins on exact fp32 distance tie ->
            // must be the lower ORIGINAL index (jnp.argmin first-wins).
            float a = s_val[klo], b = s_val[klo + 1];
            if (s_orig[klo] < s_orig[klo + 1]) { pq.x = a; pq.y = b; }
            else                               { pq.x = b; pq.y = a; }
        } else {
            // >1 boundary in one cell (pathological spacing): exact-scan sentinel.
            pq.x = __int_as_float(0x7FC00000);
            pq.y = pq.x;
        }
        g_cells[j] = pq;
    }
}

// ---------------------------------------------------------------- main ----
__device__ __forceinline__ float quant1(float x, float S, float B,
                                        const float2* __restrict__ cells,
                                        const float* __restrict__ co) {
    float u = fmaf(x, S, B);
    u = fminf(fmaxf(u, 1.0f), __uint_as_float(0x3FFFFFFFu));  // clamp to [1, 2)
    unsigned j = (__float_as_uint(u) >> 11) & 0xFFFu;         // floor((u-1)*4096)
    float2 pq = cells[j];
    float dP = x - pq.x;
    float dQ = x - pq.y;
    float r = (fabsf(dQ) < fabsf(dP)) ? pq.y : pq.x;          // tie -> p
    if (r != r) {  // NaN sentinel: exact 16-way scan (original order, first-min)
        float bd = fabsf(x - co[0]);
        r = co[0];
#pragma unroll
        for (int m = 1; m < NC; ++m) {
            float d = fabsf(x - co[m]);
            if (d < bd) { bd = d; r = co[m]; }
        }
    }
    return r;
}

__global__ void __launch_bounds__(256) main_kernel(
    const float4* __restrict__ x4, float4* __restrict__ out4, int n4,
    const float* __restrict__ x, float* __restrict__ out,
    int tail_start, int n, const float* __restrict__ center)
{
    __shared__ float2 s_cells[NCELLS];   // 32 KB
    __shared__ float  s_co[NC];

    // Stage the cell table (L2-hot after first blocks) and original centers.
    {
        const float4* gsrc = (const float4*)g_cells;
        float4* sdst = (float4*)s_cells;
        for (int i = threadIdx.x; i < NCELLS / 2; i += 256) sdst[i] = gsrc[i];
        if (threadIdx.x < NC) s_co[threadIdx.x] = center[threadIdx.x];
    }
    __syncthreads();

    float2 SB = g_affine;
    float S = SB.x, Bc = SB.y;

    int stride = gridDim.x * blockDim.x;
    int i0 = blockIdx.x * blockDim.x + threadIdx.x;

#pragma unroll 4
    for (int i = i0; i < n4; i += stride) {
        float4 v = x4[i];
        float4 r;
        r.x = quant1(v.x, S, Bc, s_cells, s_co);
        r.y = quant1(v.y, S, Bc, s_cells, s_co);
        r.z = quant1(v.z, S, Bc, s_cells, s_co);
        r.w = quant1(v.w, S, Bc, s_cells, s_co);
        out4[i] = r;
    }
    for (int i = tail_start + i0; i < n; i += stride) {
        out[i] = quant1(x[i], S, Bc, s_cells, s_co);
    }
}

// -------------------------------------------------------------- launch ----
extern "C" void kernel_launch(void* const* d_in, const int* in_sizes, int n_in,
                              void* d_out, int out_size) {
    const float* xp     = (const float*)d_in[0];
    const float* center = (const float*)d_in[1];
    float* outp         = (float*)d_out;

    int n = in_sizes[0];

    prep_kernel<<<1, 256>>>(center);

    bool aligned = ((((uintptr_t)xp) | ((uintptr_t)outp)) & 0xF) == 0;
    int n4 = aligned ? (n >> 2) : 0;
    int tail_start = n4 << 2;

    int blocks = 1024;
    main_kernel<<<blocks, 256>>>((const float4*)xp, (float4*)outp, n4,
                                 xp, outp, tail_start, n, center);
}

// round 6
// speedup vs baseline: 1.4497x; 1.2283x over previous
#include <cuda_runtime.h>
#include <cuda_bf16.h>
#include <stdint.h>
#include <math.h>

// out[i] = center[argmin_m |x[i] - center[m]|]  (exact jnp.argmin, first-min
// wins). Forward value of the straight-through soft quantizer.
//
// 15 Voronoi boundaries -> 2048-cell interval table; each cell stores its <=2
// candidate centers, tie-ordered. Main kernel: FFMA + bit-trick index, one
// LDS.64, one exact 2-way fp32 distance compare.

#define NC      16
#define NCELLS  2048

__device__ float2 g_cells[NCELLS];
__device__ float2 g_affine;  // {S, B}: u = fma(x, S, B) maps boundary span to [1,2)

// ---------------------------------------------------------------- prep ----
__global__ void prep_kernel(const float* __restrict__ center) {
    __shared__ float  s_val[NC];
    __shared__ int    s_orig[NC];
    __shared__ double s_thr[NC - 1];
    __shared__ float  s_SB[2];

    int t = threadIdx.x;

    // Stable rank sort (equal values keep original order).
    if (t < NC) {
        float ct = center[t];
        int rank = 0;
        for (int j = 0; j < NC; ++j) {
            float cj = center[j];
            if (cj < ct || (cj == ct && j < t)) rank++;
        }
        s_val[rank]  = ct;
        s_orig[rank] = t;
    }
    __syncthreads();

    if (t == 0) {
        for (int r = 0; r < NC - 1; ++r)
            s_thr[r] = 0.5 * ((double)s_val[r] + (double)s_val[r + 1]);
        double lo = s_thr[0], hi = s_thr[NC - 2];
        float S, B;
        if (hi - lo > 1e-30) {
            S = (float)(1.0 / (hi - lo));
            B = (float)(1.0 - lo * (double)S);
        } else {           // degenerate spacing: everything -> sentinel path
            S = 0.0f; B = 1.5f;
        }
        s_SB[0] = S; s_SB[1] = B;
        g_affine = make_float2(S, B);
    }
    __syncthreads();

    double S = (double)s_SB[0], B = (double)s_SB[1];
    const double slack = 4e-6;  // u-units; cell width 4.88e-4; fp32 fma err ~1e-7

    for (int j = t; j < NCELLS; j += blockDim.x) {
        double xlo, xhi;
        if (S == 0.0) { xlo = -INFINITY; xhi = INFINITY; }
        else {
            xlo = (j == 0) ? -INFINITY
                 : ((1.0 + (double)j / NCELLS - slack) - B) / S;
            xhi = (j == NCELLS - 1) ? INFINITY
                 : ((1.0 + (double)(j + 1) / NCELLS + slack) - B) / S;
        }
        int klo = 0, nb = 0;
        for (int r = 0; r < NC - 1; ++r) {
            double th = s_thr[r];
            if (th <= xlo) klo++;
            else if (th < xhi) nb++;
        }
        float2 pq;
        if (nb == 0) {
            pq.x = s_val[klo]; pq.y = s_val[klo];
        } else if (nb == 1) {
            // p (stored first) wins exact fp32 ties -> must be lower ORIGINAL
            // index (jnp.argmin first-wins).
            float a = s_val[klo], b = s_val[klo + 1];
            if (s_orig[klo] < s_orig[klo + 1]) { pq.x = a; pq.y = b; }
            else                               { pq.x = b; pq.y = a; }
        } else {
            pq.x = __int_as_float(0x7FC00000);  // NaN sentinel -> exact scan
            pq.y = pq.x;
        }
        g_cells[j] = pq;
    }
}

// ---------------------------------------------------------------- main ----
__device__ __forceinline__ float quant1(float x, float S, float B,
                                        const float2* __restrict__ cells,
                                        const float* __restrict__ co) {
    float u = fmaf(x, S, B);
    u = fminf(fmaxf(u, 1.0f), __uint_as_float(0x3FFFFFFFu));  // clamp [1,2)
    unsigned j = (__float_as_uint(u) >> 12) & 0x7FFu;         // floor((u-1)*2048)
    float2 pq = cells[j];
    float dP = x - pq.x;
    float dQ = x - pq.y;
    float r = (fabsf(dQ) < fabsf(dP)) ? pq.y : pq.x;          // tie -> p
    if (r != r) {  // NaN sentinel: exact 16-way scan, original order, first-min
        float bd = fabsf(x - co[0]);
        r = co[0];
#pragma unroll
        for (int m = 1; m < NC; ++m) {
            float d = fabsf(x - co[m]);
            if (d < bd) { bd = d; r = co[m]; }
        }
    }
    return r;
}

__device__ __forceinline__ float4 quant4(float4 v, float S, float B,
                                         const float2* __restrict__ cells,
                                         const float* __restrict__ co) {
    float4 r;
    r.x = quant1(v.x, S, B, cells, co);
    r.y = quant1(v.y, S, B, cells, co);
    r.z = quant1(v.z, S, B, cells, co);
    r.w = quant1(v.w, S, B, cells, co);
    return r;
}

__global__ void __launch_bounds__(256) main_kernel(
    const float4* __restrict__ x4, float4* __restrict__ out4, int n4,
    const float* __restrict__ x, float* __restrict__ out,
    int tail_start, int n, const float* __restrict__ center)
{
    __shared__ float2 s_cells[NCELLS];   // 16 KB
    __shared__ float  s_co[NC];

    {
        const float4* __restrict__ gsrc = (const float4*)g_cells;
        float4* __restrict__ sdst = (float4*)s_cells;
#pragma unroll
        for (int i = threadIdx.x; i < NCELLS / 2; i += 256) sdst[i] = gsrc[i];
        if (threadIdx.x < NC) s_co[threadIdx.x] = center[threadIdx.x];
    }
    __syncthreads();

    float2 SB = g_affine;
    float S = SB.x, Bc = SB.y;

    int stride = gridDim.x * blockDim.x;
    int i0 = blockIdx.x * blockDim.x + threadIdx.x;

    // 2x unrolled grid-stride: both loads in flight before either lookup.
    int i = i0;
    for (; i + stride < n4; i += 2 * stride) {
        float4 a = x4[i];
        float4 b = x4[i + stride];
        float4 ra = quant4(a, S, Bc, s_cells, s_co);
        float4 rb = quant4(b, S, Bc, s_cells, s_co);
        out4[i] = ra;
        out4[i + stride] = rb;
    }
    for (; i < n4; i += stride) {
        out4[i] = quant4(x4[i], S, Bc, s_cells, s_co);
    }
    for (int k = tail_start + i0; k < n; k += stride) {
        out[k] = quant1(x[k], S, Bc, s_cells, s_co);
    }
}

// -------------------------------------------------------------- launch ----
extern "C" void kernel_launch(void* const* d_in, const int* in_sizes, int n_in,
                              void* d_out, int out_size) {
    const float* xp     = (const float*)d_in[0];
    const float* center = (const float*)d_in[1];
    float* outp         = (float*)d_out;

    int n = in_sizes[0];

    prep_kernel<<<1, 256>>>(center);

    bool aligned = ((((uintptr_t)xp) | ((uintptr_t)outp)) & 0xF) == 0;
    int n4 = aligned ? (n >> 2) : 0;
    int tail_start = n4 << 2;

    // 148 SMs x 8 blocks/SM = one exact full wave (grid-stride loop keeps this
    // correct on any SM count).
    int blocks = 148 * 8;

    main_kernel<<<blocks, 256>>>((const float4*)xp, (float4*)outp, n4,
                                 xp, outp, tail_start, n, center);
}